// round 2
// baseline (speedup 1.0000x reference)
#include <cuda_runtime.h>
#include <math.h>

// NT-Xent loss, N=4096, D=256.
// loss = mean_i( log(sum_{j!=i} exp(2*dot(zn_i,zn_j))) - 2*dot(zn_i, zn_{i^4096}) )
// Pipeline:
//   k_normalize   : zn = z / max(||z||, 1e-8), also zeroes rowsum
//   k_gemm_rowsum : fused 8192x8192x256 fp32 GEMM + exp + masked row-sum
//   k_pair        : per-row target dot + log(rowsum) -> per-row loss term
//   k_reduce      : deterministic mean -> out[0]

#define NROWS 8192
#define NHALF 4096
#define DDIM  256

__device__ __align__(16) float g_zn[NROWS * DDIM];
__device__ float g_rowsum[NROWS];
__device__ float g_li[NROWS];

// ---------------------------------------------------------------- normalize
__global__ __launch_bounds__(256) void k_normalize(const float* __restrict__ z1,
                                                   const float* __restrict__ z2) {
    const int row = blockIdx.x;          // 0..8191
    const int tid = threadIdx.x;         // 0..255, one element each
    const float* src = (row < NHALF) ? (z1 + (size_t)row * DDIM)
                                     : (z2 + (size_t)(row - NHALF) * DDIM);
    float v = src[tid];
    float ss = v * v;
    #pragma unroll
    for (int o = 16; o; o >>= 1) ss += __shfl_xor_sync(0xFFFFFFFFu, ss, o);

    __shared__ float sh[8];
    if ((tid & 31) == 0) sh[tid >> 5] = ss;
    __syncthreads();
    if (tid < 32) {
        float t = (tid < 8) ? sh[tid] : 0.0f;
        #pragma unroll
        for (int o = 4; o; o >>= 1) t += __shfl_xor_sync(0xFFFFFFFFu, t, o);
        if (tid == 0) sh[0] = 1.0f / fmaxf(sqrtf(t), 1e-8f);
    }
    __syncthreads();
    g_zn[(size_t)row * DDIM + tid] = v * sh[0];
    if (tid == 0) g_rowsum[row] = 0.0f;
}

// ------------------------------------------------- fused GEMM + exp + rowsum
// BM=128, BN=64, BK=32, 256 threads (16x16), microtile 8x4.
// Shared tiles are k-major ([k][row]) so the inner loop uses float4 LDS.
#define BM 128
#define BN 64
#define BK 32
#define JSPLIT 16
#define JCHUNK (NROWS / JSPLIT)   // 512 columns per block

__global__ __launch_bounds__(256) void k_gemm_rowsum() {
    __shared__ __align__(16) float As[BK][BM + 4];
    __shared__ __align__(16) float Bs[BK][BN + 4];
    __shared__ float red[BM][17];

    const int tid = threadIdx.x;
    const int tx = tid & 15;          // column group (4 cols)
    const int ty = tid >> 4;          // row group (8 rows)
    const int i0 = blockIdx.x * BM;
    const int jc = blockIdx.y * JCHUNK;
    const int kq = tid & 7;           // k quad within BK (4 floats)
    const int r0 = tid >> 3;          // 0..31

    float rsum[8];
    #pragma unroll
    for (int m = 0; m < 8; m++) rsum[m] = 0.0f;

    for (int jt = 0; jt < JCHUNK; jt += BN) {
        const int j0 = jc + jt;
        float acc[8][4];
        #pragma unroll
        for (int m = 0; m < 8; m++)
            #pragma unroll
            for (int c = 0; c < 4; c++) acc[m][c] = 0.0f;

        for (int kk = 0; kk < DDIM; kk += BK) {
            // load A tile 128x32 (float4 along k, coalesced per row)
            #pragma unroll
            for (int rr = 0; rr < BM; rr += 32) {
                float4 v = *(const float4*)&g_zn[(size_t)(i0 + r0 + rr) * DDIM + kk + kq * 4];
                As[kq * 4 + 0][r0 + rr] = v.x;
                As[kq * 4 + 1][r0 + rr] = v.y;
                As[kq * 4 + 2][r0 + rr] = v.z;
                As[kq * 4 + 3][r0 + rr] = v.w;
            }
            // load B tile 64x32
            #pragma unroll
            for (int rr = 0; rr < BN; rr += 32) {
                float4 v = *(const float4*)&g_zn[(size_t)(j0 + r0 + rr) * DDIM + kk + kq * 4];
                Bs[kq * 4 + 0][r0 + rr] = v.x;
                Bs[kq * 4 + 1][r0 + rr] = v.y;
                Bs[kq * 4 + 2][r0 + rr] = v.z;
                Bs[kq * 4 + 3][r0 + rr] = v.w;
            }
            __syncthreads();

            #pragma unroll
            for (int k = 0; k < BK; k++) {
                float4 a0 = *(const float4*)&As[k][ty * 8];
                float4 a1 = *(const float4*)&As[k][ty * 8 + 4];
                float4 b  = *(const float4*)&Bs[k][tx * 4];
                float am[8] = {a0.x, a0.y, a0.z, a0.w, a1.x, a1.y, a1.z, a1.w};
                float bn[4] = {b.x, b.y, b.z, b.w};
                #pragma unroll
                for (int m = 0; m < 8; m++)
                    #pragma unroll
                    for (int c = 0; c < 4; c++)
                        acc[m][c] = fmaf(am[m], bn[c], acc[m][c]);
            }
            __syncthreads();
        }

        // epilogue: sim = 2*dot; exp; mask diagonal; accumulate per-row
        #pragma unroll
        for (int m = 0; m < 8; m++) {
            const int gi = i0 + ty * 8 + m;
            #pragma unroll
            for (int c = 0; c < 4; c++) {
                const int gj = j0 + tx * 4 + c;
                float e = __expf(2.0f * acc[m][c]);
                rsum[m] += (gi == gj) ? 0.0f : e;
            }
        }
    }

    // reduce rsum across the 16 tx groups, then one atomicAdd per row
    #pragma unroll
    for (int m = 0; m < 8; m++) red[ty * 8 + m][tx] = rsum[m];
    __syncthreads();
    if (tid < BM) {
        float s = 0.0f;
        #pragma unroll
        for (int t = 0; t < 16; t++) s += red[tid][t];
        atomicAdd(&g_rowsum[i0 + tid], s);
    }
}

// ----------------------------------------------- per-row target dot + log
__global__ __launch_bounds__(256) void k_pair() {
    const int gwarp = (blockIdx.x * blockDim.x + threadIdx.x) >> 5;  // row
    const int lane = threadIdx.x & 31;
    if (gwarp >= NROWS) return;
    const float4* a = (const float4*)(g_zn + (size_t)gwarp * DDIM);
    const float4* b = (const float4*)(g_zn + (size_t)(gwarp ^ NHALF) * DDIM);
    float s = 0.0f;
    #pragma unroll
    for (int t = 0; t < 2; t++) {
        float4 av = a[lane + 32 * t];
        float4 bv = b[lane + 32 * t];
        s = fmaf(av.x, bv.x, s);
        s = fmaf(av.y, bv.y, s);
        s = fmaf(av.z, bv.z, s);
        s = fmaf(av.w, bv.w, s);
    }
    #pragma unroll
    for (int o = 16; o; o >>= 1) s += __shfl_xor_sync(0xFFFFFFFFu, s, o);
    if (lane == 0)
        g_li[gwarp] = logf(g_rowsum[gwarp]) - 2.0f * s;
}

// ----------------------------------------------------- deterministic mean
__global__ __launch_bounds__(1024) void k_reduce(float* __restrict__ out) {
    __shared__ float sh[1024];
    const int tid = threadIdx.x;
    float s = 0.0f;
    #pragma unroll
    for (int u = 0; u < NROWS / 1024; u++) s += g_li[tid + u * 1024];
    sh[tid] = s;
    __syncthreads();
    for (int off = 512; off; off >>= 1) {
        if (tid < off) sh[tid] += sh[tid + off];
        __syncthreads();
    }
    if (tid == 0) out[0] = sh[0] * (1.0f / (float)NROWS);
}

// ---------------------------------------------------------------- launch
extern "C" void kernel_launch(void* const* d_in, const int* in_sizes, int n_in,
                              void* d_out, int out_size) {
    const float* z1 = (const float*)d_in[0];
    const float* z2 = (const float*)d_in[1];
    float* out = (float*)d_out;

    k_normalize<<<NROWS, 256>>>(z1, z2);
    dim3 grid(NROWS / BM, JSPLIT);       // (64, 16)
    k_gemm_rowsum<<<grid, 256>>>();
    k_pair<<<NROWS / 8, 256>>>();        // 8 warps/block, 1 row/warp
    k_reduce<<<1, 1024>>>(out);
}

// round 5
// speedup vs baseline: 5.6807x; 5.6807x over previous
#include <cuda_runtime.h>
#include <cuda_bf16.h>
#include <cstdint>
#include <math.h>

// NT-Xent loss, N=4096, D=256.
// loss = mean_i( log(sum_{j!=i} e^{2 zn_i.zn_j}) - 2 zn_i.zn_{i^4096} )
// R5: R4 HMMA pipeline + cross-warp (wn) smem reduction of row sums
//     (R4 bug: 4 warps plain-stored the same rows -> rowsum/4 -> rel_err 0.154).

#define NROWS 8192
#define NHALF 4096
#define DDIM  256
#define BM 128
#define BN 128
#define JSPLIT 4
#define JTILES (NROWS / JSPLIT / BN)     // 16 j-tiles per CTA
#define TILE_BYTES (BM * DDIM * 2)       // 65536 bytes (128 x 256 bf16)
#define RED_BYTES (4 * BM * 4)           // [wn][row] float partials

__device__ __align__(16) float g_zn[NROWS * DDIM];
__device__ __align__(16) __nv_bfloat16 g_zb[NROWS * DDIM];
__device__ float g_rspart[JSPLIT][NROWS];
__device__ float g_li[NROWS];

// ---------------------------------------------------------------- helpers
__device__ __forceinline__ uint32_t smem_u32(const void* p) {
    uint32_t a;
    asm("{ .reg .u64 t; cvta.to.shared.u64 t, %1; cvt.u32.u64 %0, t; }" : "=r"(a) : "l"(p));
    return a;
}
__device__ __forceinline__ void ldsm_x4(uint32_t addr, uint32_t* r) {
    asm volatile("ldmatrix.sync.aligned.m8n8.x4.shared.b16 {%0,%1,%2,%3}, [%4];"
        : "=r"(r[0]), "=r"(r[1]), "=r"(r[2]), "=r"(r[3]) : "r"(addr));
}
__device__ __forceinline__ void mma16816(float* c, const uint32_t* a, const uint32_t* b) {
    asm volatile("mma.sync.aligned.m16n8k16.row.col.f32.bf16.bf16.f32 "
        "{%0,%1,%2,%3}, {%4,%5,%6,%7}, {%8,%9}, {%0,%1,%2,%3};"
        : "+f"(c[0]), "+f"(c[1]), "+f"(c[2]), "+f"(c[3])
        : "r"(a[0]), "r"(a[1]), "r"(a[2]), "r"(a[3]), "r"(b[0]), "r"(b[1]));
}
__device__ __forceinline__ void cp_async16(uint32_t dst, const void* src) {
    asm volatile("cp.async.cg.shared.global [%0], [%1], 16;" :: "r"(dst), "l"(src));
}
#define CP_COMMIT() asm volatile("cp.async.commit_group;" ::: "memory")
#define CP_WAIT0()  asm volatile("cp.async.wait_group 0;" ::: "memory")

// Tile smem layout: row stride 512B (256 bf16), 32 x 16B chunks per row,
// chunk swizzle c' = c ^ (row & 7)  -> conflict-free STS + ldmatrix.
__device__ __forceinline__ uint32_t tile_addr(uint32_t base, int row, int chunk) {
    return base + (uint32_t)row * 512u + (uint32_t)((chunk ^ (row & 7)) << 4);
}

// ---------------------------------------------------------------- normalize
__global__ __launch_bounds__(256) void k_normalize(const float* __restrict__ z1,
                                                   const float* __restrict__ z2) {
    const int row = blockIdx.x;
    const int tid = threadIdx.x;
    const float* src = (row < NHALF) ? (z1 + (size_t)row * DDIM)
                                     : (z2 + (size_t)(row - NHALF) * DDIM);
    float v = src[tid];
    float ss = v * v;
    #pragma unroll
    for (int o = 16; o; o >>= 1) ss += __shfl_xor_sync(0xFFFFFFFFu, ss, o);
    __shared__ float sh[8];
    if ((tid & 31) == 0) sh[tid >> 5] = ss;
    __syncthreads();
    if (tid < 32) {
        float t = (tid < 8) ? sh[tid] : 0.0f;
        #pragma unroll
        for (int o = 4; o; o >>= 1) t += __shfl_xor_sync(0xFFFFFFFFu, t, o);
        if (tid == 0) sh[0] = 1.0f / fmaxf(sqrtf(t), 1e-8f);
    }
    __syncthreads();
    float zv = v * sh[0];
    g_zn[(size_t)row * DDIM + tid] = zv;
    g_zb[(size_t)row * DDIM + tid] = __float2bfloat16(zv);
}

// --------------------------------------------- HMMA GEMM + exp + rowsum
__global__ __launch_bounds__(256, 1) void k_gemm_tc() {
    extern __shared__ __align__(16) char dyn[];
    const int tid = threadIdx.x;
    const int wid = tid >> 5;
    const int lane = tid & 31;
    const int wm = wid & 1;          // warp row (64 rows each)
    const int wn = wid >> 1;         // warp col (32 cols each)
    const int i0 = blockIdx.x * BM;
    const int jbase = blockIdx.y * (NROWS / JSPLIT);

    uint32_t d32 = smem_u32(dyn);
    char* base = dyn + ((1024u - (d32 & 1023u)) & 1023u);
    const uint32_t uA = smem_u32(base);
    const uint32_t uB0 = uA + TILE_BYTES;
    const uint32_t uB1 = uA + 2 * TILE_BYTES;
    float* red = (float*)(base + 3 * TILE_BYTES);   // [4][BM]

    // prologue: async-load A tile and B tile 0
    #pragma unroll
    for (int it = 0; it < 16; it++) {
        int idx = tid + it * 256;        // 4096 chunks
        int r = idx >> 5, c = idx & 31;
        cp_async16(tile_addr(uA, r, c),  g_zb + (size_t)(i0 + r) * DDIM + c * 8);
        cp_async16(tile_addr(uB0, r, c), g_zb + (size_t)(jbase + r) * DDIM + c * 8);
    }
    CP_COMMIT();
    CP_WAIT0();
    __syncthreads();

    float rsum[8];                       // [mf][lo/hi] row partial sums
    #pragma unroll
    for (int m = 0; m < 8; m++) rsum[m] = 0.0f;

    const int rlo_base = i0 + wm * 64 + (lane >> 2);

    for (int jt = 0; jt < JTILES; jt++) {
        const uint32_t uBc = (jt & 1) ? uB1 : uB0;
        const int jn = jt + 1;
        // prefetch next B tile into the other buffer
        if (jn < JTILES) {
            const uint32_t uBn = (jn & 1) ? uB1 : uB0;
            #pragma unroll
            for (int it = 0; it < 16; it++) {
                int idx = tid + it * 256;
                int r = idx >> 5, c = idx & 31;
                cp_async16(tile_addr(uBn, r, c),
                           g_zb + (size_t)(jbase + jn * BN + r) * DDIM + c * 8);
            }
            CP_COMMIT();
        }

        float acc[4][4][4];
        #pragma unroll
        for (int mf = 0; mf < 4; mf++)
            #pragma unroll
            for (int nf = 0; nf < 4; nf++)
                #pragma unroll
                for (int c = 0; c < 4; c++) acc[mf][nf][c] = 0.0f;

        #pragma unroll 4
        for (int ks = 0; ks < 16; ks++) {
            const int cch = ks * 2 + (lane >> 4);
            uint32_t af[4][4], bf[4][2];
            #pragma unroll
            for (int mf = 0; mf < 4; mf++) {
                int r = wm * 64 + mf * 16 + (lane & 15);
                ldsm_x4(tile_addr(uA, r, cch), af[mf]);
            }
            #pragma unroll
            for (int ng = 0; ng < 2; ng++) {
                int rn = wn * 32 + ng * 16 + (lane & 15);
                uint32_t q[4];
                ldsm_x4(tile_addr(uBc, rn, cch), q);
                bf[ng * 2 + 0][0] = q[0]; bf[ng * 2 + 0][1] = q[2];
                bf[ng * 2 + 1][0] = q[1]; bf[ng * 2 + 1][1] = q[3];
            }
            #pragma unroll
            for (int mf = 0; mf < 4; mf++)
                #pragma unroll
                for (int nf = 0; nf < 4; nf++)
                    mma16816(acc[mf][nf], af[mf], bf[nf]);
        }

        // epilogue (registers only): exp + diagonal mask + row partials.
        // overlaps the in-flight cp.async prefetch.
        const int jt0 = jbase + jt * BN + wn * 32 + (lane & 3) * 2;
        #pragma unroll
        for (int mf = 0; mf < 4; mf++) {
            const int rlo = rlo_base + mf * 16;
            const int rhi = rlo + 8;
            float slo = 0.0f, shi = 0.0f;
            #pragma unroll
            for (int nf = 0; nf < 4; nf++) {
                const int col = jt0 + nf * 8;
                float e0 = __expf(2.0f * acc[mf][nf][0]);
                float e1 = __expf(2.0f * acc[mf][nf][1]);
                float e2 = __expf(2.0f * acc[mf][nf][2]);
                float e3 = __expf(2.0f * acc[mf][nf][3]);
                slo += (rlo == col)     ? 0.0f : e0;
                slo += (rlo == col + 1) ? 0.0f : e1;
                shi += (rhi == col)     ? 0.0f : e2;
                shi += (rhi == col + 1) ? 0.0f : e3;
            }
            rsum[mf * 2] += slo;
            rsum[mf * 2 + 1] += shi;
        }

        CP_WAIT0();
        __syncthreads();
    }

    // quad-reduce (lanes sharing a row), stage per-wn partials in smem,
    // then threads 0..127 sum the 4 wn partials -> one deterministic store.
    #pragma unroll
    for (int mf = 0; mf < 4; mf++) {
        float slo = rsum[mf * 2], shi = rsum[mf * 2 + 1];
        slo += __shfl_xor_sync(0xFFFFFFFFu, slo, 1);
        slo += __shfl_xor_sync(0xFFFFFFFFu, slo, 2);
        shi += __shfl_xor_sync(0xFFFFFFFFu, shi, 1);
        shi += __shfl_xor_sync(0xFFFFFFFFu, shi, 2);
        if ((lane & 3) == 0) {
            const int lrow = wm * 64 + mf * 16 + (lane >> 2);
            red[wn * BM + lrow] = slo;
            red[wn * BM + lrow + 8] = shi;
        }
    }
    __syncthreads();
    if (tid < BM) {
        float s = red[tid] + red[BM + tid] + red[2 * BM + tid] + red[3 * BM + tid];
        g_rspart[blockIdx.y][i0 + tid] = s;
    }
}

// ----------------------------------------------- per-row target dot + log
__global__ __launch_bounds__(256) void k_pair() {
    const int gwarp = (blockIdx.x * blockDim.x + threadIdx.x) >> 5;
    const int lane = threadIdx.x & 31;
    if (gwarp >= NROWS) return;
    const float4* a = (const float4*)(g_zn + (size_t)gwarp * DDIM);
    const float4* b = (const float4*)(g_zn + (size_t)(gwarp ^ NHALF) * DDIM);
    float s = 0.0f;
    #pragma unroll
    for (int t = 0; t < 2; t++) {
        float4 av = a[lane + 32 * t];
        float4 bv = b[lane + 32 * t];
        s = fmaf(av.x, bv.x, s);
        s = fmaf(av.y, bv.y, s);
        s = fmaf(av.z, bv.z, s);
        s = fmaf(av.w, bv.w, s);
    }
    #pragma unroll
    for (int o = 16; o; o >>= 1) s += __shfl_xor_sync(0xFFFFFFFFu, s, o);
    if (lane == 0) {
        float rs = g_rspart[0][gwarp] + g_rspart[1][gwarp]
                 + g_rspart[2][gwarp] + g_rspart[3][gwarp];
        g_li[gwarp] = logf(rs) - 2.0f * s;
    }
}

// ----------------------------------------------------- deterministic mean
__global__ __launch_bounds__(1024) void k_reduce(float* __restrict__ out) {
    __shared__ float sh[1024];
    const int tid = threadIdx.x;
    float s = 0.0f;
    #pragma unroll
    for (int u = 0; u < NROWS / 1024; u++) s += g_li[tid + u * 1024];
    sh[tid] = s;
    __syncthreads();
    for (int off = 512; off; off >>= 1) {
        if (tid < off) sh[tid] += sh[tid + off];
        __syncthreads();
    }
    if (tid == 0) out[0] = sh[0] * (1.0f / (float)NROWS);
}

// ---------------------------------------------------------------- launch
extern "C" void kernel_launch(void* const* d_in, const int* in_sizes, int n_in,
                              void* d_out, int out_size) {
    const float* z1 = (const float*)d_in[0];
    const float* z2 = (const float*)d_in[1];
    float* out = (float*)d_out;

    static int smem_set = 0;
    if (!smem_set) {
        cudaFuncSetAttribute(k_gemm_tc, cudaFuncAttributeMaxDynamicSharedMemorySize,
                             3 * TILE_BYTES + RED_BYTES + 1024);
        smem_set = 1;
    }

    k_normalize<<<NROWS, 256>>>(z1, z2);
    dim3 grid(NROWS / BM, JSPLIT);       // (64, 4) = 256 CTAs
    k_gemm_tc<<<grid, 256, 3 * TILE_BYTES + RED_BYTES + 1024>>>();
    k_pair<<<NROWS / 8, 256>>>();
    k_reduce<<<1, 1024>>>(out);
}

// round 6
// speedup vs baseline: 10.6800x; 1.8800x over previous
#include <cuda_runtime.h>
#include <cuda_bf16.h>
#include <cstdint>
#include <math.h>

// NT-Xent loss, N=4096, D=256.
// loss = mean_i( log(sum_{j!=i} e^{2 zn_i.zn_j}) - 2 zn_i.zn_{i^4096} )
// R6: symmetric Gram — compute only upper-triangle 128x128 tiles (2080 of 4096),
// scatter row- AND column-sums via atomicAdd. Persistent 148-CTA grid, balanced
// static chunks over interleaved row order (0,63,1,62,...). HMMA bf16 core from R5.

#define NROWS 8192
#define NHALF 4096
#define DDIM  256
#define BM 128
#define NTILE 64                          // 8192/128 row tiles
#define TOTTILES 2080                     // 64*65/2
#define NCTA 148
#define TILE_BYTES (BM * DDIM * 2)        // 65536 bytes (128 x 256 bf16)
#define RED_BYTES ((4 + 2) * BM * 4)      // red_row[4][128] + red_col[2][128]

__device__ __align__(16) float g_zn[NROWS * DDIM];
__device__ __align__(16) __nv_bfloat16 g_zb[NROWS * DDIM];
__device__ float g_rowsum[NROWS];
__device__ float g_li[NROWS];

// ---------------------------------------------------------------- helpers
__device__ __forceinline__ uint32_t smem_u32(const void* p) {
    uint32_t a;
    asm("{ .reg .u64 t; cvta.to.shared.u64 t, %1; cvt.u32.u64 %0, t; }" : "=r"(a) : "l"(p));
    return a;
}
__device__ __forceinline__ void ldsm_x4(uint32_t addr, uint32_t* r) {
    asm volatile("ldmatrix.sync.aligned.m8n8.x4.shared.b16 {%0,%1,%2,%3}, [%4];"
        : "=r"(r[0]), "=r"(r[1]), "=r"(r[2]), "=r"(r[3]) : "r"(addr));
}
__device__ __forceinline__ void mma16816(float* c, const uint32_t* a, const uint32_t* b) {
    asm volatile("mma.sync.aligned.m16n8k16.row.col.f32.bf16.bf16.f32 "
        "{%0,%1,%2,%3}, {%4,%5,%6,%7}, {%8,%9}, {%0,%1,%2,%3};"
        : "+f"(c[0]), "+f"(c[1]), "+f"(c[2]), "+f"(c[3])
        : "r"(a[0]), "r"(a[1]), "r"(a[2]), "r"(a[3]), "r"(b[0]), "r"(b[1]));
}
__device__ __forceinline__ void cp_async16(uint32_t dst, const void* src) {
    asm volatile("cp.async.cg.shared.global [%0], [%1], 16;" :: "r"(dst), "l"(src));
}
#define CP_COMMIT() asm volatile("cp.async.commit_group;" ::: "memory")
#define CP_WAIT0()  asm volatile("cp.async.wait_group 0;" ::: "memory")

// Tile smem layout: row stride 512B (256 bf16), 32 x 16B chunks per row,
// chunk swizzle c' = c ^ (row & 7) -> conflict-free STS + ldmatrix.
__device__ __forceinline__ uint32_t tile_addr(uint32_t base, int row, int chunk) {
    return base + (uint32_t)row * 512u + (uint32_t)((chunk ^ (row & 7)) << 4);
}
// interleaved row order: p -> row (long rows alternate with short ones)
__device__ __forceinline__ int rowof(int p) {
    return (p & 1) ? (NTILE - 1 - (p >> 1)) : (p >> 1);
}
__device__ __forceinline__ void tile_load(uint32_t ubase, int row0, int tid) {
    #pragma unroll
    for (int it = 0; it < 16; it++) {
        int idx = tid + it * 256;
        int r = idx >> 5, c = idx & 31;
        cp_async16(tile_addr(ubase, r, c), g_zb + (size_t)(row0 + r) * DDIM + c * 8);
    }
}

// ---------------------------------------------------------------- normalize
__global__ __launch_bounds__(256) void k_normalize(const float* __restrict__ z1,
                                                   const float* __restrict__ z2) {
    const int row = blockIdx.x;
    const int tid = threadIdx.x;
    const float* src = (row < NHALF) ? (z1 + (size_t)row * DDIM)
                                     : (z2 + (size_t)(row - NHALF) * DDIM);
    float v = src[tid];
    float ss = v * v;
    #pragma unroll
    for (int o = 16; o; o >>= 1) ss += __shfl_xor_sync(0xFFFFFFFFu, ss, o);
    __shared__ float sh[8];
    if ((tid & 31) == 0) sh[tid >> 5] = ss;
    __syncthreads();
    if (tid < 32) {
        float t = (tid < 8) ? sh[tid] : 0.0f;
        #pragma unroll
        for (int o = 4; o; o >>= 1) t += __shfl_xor_sync(0xFFFFFFFFu, t, o);
        if (tid == 0) sh[0] = 1.0f / fmaxf(sqrtf(t), 1e-8f);
    }
    __syncthreads();
    float zv = v * sh[0];
    g_zn[(size_t)row * DDIM + tid] = zv;
    g_zb[(size_t)row * DDIM + tid] = __float2bfloat16(zv);
    if (tid == 0) g_rowsum[row] = 0.0f;
}

// --------------------------------------------- symmetric HMMA GEMM + exp + sums
__global__ __launch_bounds__(256, 1) void k_gemm_tc() {
    extern __shared__ __align__(16) char dyn[];
    const int tid = threadIdx.x;
    const int wid = tid >> 5;
    const int lane = tid & 31;
    const int wm = wid & 1;          // warp row (64 rows each)
    const int wn = wid >> 1;         // warp col (32 cols each)
    const int cta = blockIdx.x;

    uint32_t d32 = smem_u32(dyn);
    char* base = dyn + ((1024u - (d32 & 1023u)) & 1023u);
    const uint32_t uA  = smem_u32(base);
    const uint32_t uB0 = uA + TILE_BYTES;
    const uint32_t uB1 = uA + 2 * TILE_BYTES;
    float* red_row = (float*)(base + 3 * TILE_BYTES);   // [4][128]
    float* red_col = red_row + 4 * BM;                  // [2][128]

    // balanced static chunk: first 8 CTAs get 15 tiles, rest 14 (148*14+8 = 2080)
    const int count = 14 + (cta < 8 ? 1 : 0);
    int rem = cta * 14 + (cta < 8 ? cta : 8);
    int p = 0;
    for (;;) {
        int L = NTILE - rowof(p);
        if (rem < L) break;
        rem -= L;
        p++;
    }
    int off = rem;

    // prologue: load A(ti0), B(tj0) -> buf0
    int ti = rowof(p);
    tile_load(uA, ti * BM, tid);
    tile_load(uB0, (ti + off) * BM, tid);
    CP_COMMIT();
    int cur_ti = ti;

    for (int k = 0; k < count; k++) {
        ti = rowof(p);
        const int tj = ti + off;
        if (ti != cur_ti) {              // row switch: reload A (short bubble)
            tile_load(uA, ti * BM, tid);
            CP_COMMIT();
            cur_ti = ti;
        }
        CP_WAIT0();
        __syncthreads();

        // prefetch next tile's B into the other buffer
        if (k + 1 < count) {
            int p2 = p, o2 = off + 1;
            if (o2 >= NTILE - rowof(p2)) { o2 = 0; p2++; }
            tile_load((k & 1) ? uB0 : uB1, (rowof(p2) + o2) * BM, tid);
            CP_COMMIT();
        }

        const uint32_t uBc = (k & 1) ? uB1 : uB0;
        const int i0 = ti * BM, j0 = tj * BM;
        const bool diag = (ti == tj);

        float acc[4][4][4];
        #pragma unroll
        for (int mf = 0; mf < 4; mf++)
            #pragma unroll
            for (int nf = 0; nf < 4; nf++)
                #pragma unroll
                for (int c = 0; c < 4; c++) acc[mf][nf][c] = 0.0f;

        #pragma unroll 4
        for (int ks = 0; ks < 16; ks++) {
            const int cch = ks * 2 + (lane >> 4);
            uint32_t af[4][4], bf[4][2];
            #pragma unroll
            for (int mf = 0; mf < 4; mf++) {
                int r = wm * 64 + mf * 16 + (lane & 15);
                ldsm_x4(tile_addr(uA, r, cch), af[mf]);
            }
            #pragma unroll
            for (int ng = 0; ng < 2; ng++) {
                int rn = wn * 32 + ng * 16 + (lane & 15);
                uint32_t q[4];
                ldsm_x4(tile_addr(uBc, rn, cch), q);
                bf[ng * 2 + 0][0] = q[0]; bf[ng * 2 + 0][1] = q[2];
                bf[ng * 2 + 1][0] = q[1]; bf[ng * 2 + 1][1] = q[3];
            }
            #pragma unroll
            for (int mf = 0; mf < 4; mf++)
                #pragma unroll
                for (int nf = 0; nf < 4; nf++)
                    mma16816(acc[mf][nf], af[mf], bf[nf]);
        }

        // ---- epilogue: exp, diagonal mask, row sums + column sums ----
        const int rloc = wm * 64 + (lane >> 2);          // local row (lo)
        const int cloc = wn * 32 + (lane & 3) * 2;       // local col base
        float cs[8];
        #pragma unroll
        for (int x = 0; x < 8; x++) cs[x] = 0.0f;

        #pragma unroll
        for (int mf = 0; mf < 4; mf++) {
            const int rlo = i0 + rloc + mf * 16;
            const int rhi = rlo + 8;
            float slo = 0.0f, shi = 0.0f;
            #pragma unroll
            for (int nf = 0; nf < 4; nf++) {
                const int col = j0 + cloc + nf * 8;
                float e0 = __expf(2.0f * acc[mf][nf][0]);
                float e1 = __expf(2.0f * acc[mf][nf][1]);
                float e2 = __expf(2.0f * acc[mf][nf][2]);
                float e3 = __expf(2.0f * acc[mf][nf][3]);
                e0 = (rlo == col)     ? 0.0f : e0;
                e1 = (rlo == col + 1) ? 0.0f : e1;
                e2 = (rhi == col)     ? 0.0f : e2;
                e3 = (rhi == col + 1) ? 0.0f : e3;
                slo += e0 + e1;
                shi += e2 + e3;
                cs[nf * 2]     += e0 + e2;
                cs[nf * 2 + 1] += e1 + e3;
            }
            // quad-reduce rows (lanes sharing a row differ in lane&3)
            slo += __shfl_xor_sync(0xFFFFFFFFu, slo, 1);
            slo += __shfl_xor_sync(0xFFFFFFFFu, slo, 2);
            shi += __shfl_xor_sync(0xFFFFFFFFu, shi, 1);
            shi += __shfl_xor_sync(0xFFFFFFFFu, shi, 2);
            if ((lane & 3) == 0) {
                const int lrow = wm * 64 + mf * 16 + (lane >> 2);
                red_row[wn * BM + lrow] = slo;
                red_row[wn * BM + lrow + 8] = shi;
            }
        }
        if (!diag) {
            // reduce cols across the 8 row-groups (xor 4, 8, 16)
            #pragma unroll
            for (int x = 0; x < 8; x++) {
                cs[x] += __shfl_xor_sync(0xFFFFFFFFu, cs[x], 4);
                cs[x] += __shfl_xor_sync(0xFFFFFFFFu, cs[x], 8);
                cs[x] += __shfl_xor_sync(0xFFFFFFFFu, cs[x], 16);
            }
            if (lane < 4) {
                #pragma unroll
                for (int nf = 0; nf < 4; nf++) {
                    const int c = wn * 32 + nf * 8 + lane * 2;
                    red_col[wm * BM + c]     = cs[nf * 2];
                    red_col[wm * BM + c + 1] = cs[nf * 2 + 1];
                }
            }
        }
        __syncthreads();
        if (tid < BM) {
            float s = red_row[tid] + red_row[BM + tid]
                    + red_row[2 * BM + tid] + red_row[3 * BM + tid];
            atomicAdd(&g_rowsum[i0 + tid], s);
        } else if (!diag) {
            const int c = tid - BM;
            atomicAdd(&g_rowsum[j0 + c], red_col[c] + red_col[BM + c]);
        }

        off++;
        if (off >= NTILE - ti) { off = 0; p++; }
    }
}

// ----------------------------------------------- per-row target dot + log
__global__ __launch_bounds__(256) void k_pair() {
    const int gwarp = (blockIdx.x * blockDim.x + threadIdx.x) >> 5;
    const int lane = threadIdx.x & 31;
    if (gwarp >= NROWS) return;
    const float4* a = (const float4*)(g_zn + (size_t)gwarp * DDIM);
    const float4* b = (const float4*)(g_zn + (size_t)(gwarp ^ NHALF) * DDIM);
    float s = 0.0f;
    #pragma unroll
    for (int t = 0; t < 2; t++) {
        float4 av = a[lane + 32 * t];
        float4 bv = b[lane + 32 * t];
        s = fmaf(av.x, bv.x, s);
        s = fmaf(av.y, bv.y, s);
        s = fmaf(av.z, bv.z, s);
        s = fmaf(av.w, bv.w, s);
    }
    #pragma unroll
    for (int o = 16; o; o >>= 1) s += __shfl_xor_sync(0xFFFFFFFFu, s, o);
    if (lane == 0)
        g_li[gwarp] = logf(g_rowsum[gwarp]) - 2.0f * s;
}

// ----------------------------------------------------- deterministic mean
__global__ __launch_bounds__(1024) void k_reduce(float* __restrict__ out) {
    __shared__ float sh[1024];
    const int tid = threadIdx.x;
    float s = 0.0f;
    #pragma unroll
    for (int u = 0; u < NROWS / 1024; u++) s += g_li[tid + u * 1024];
    sh[tid] = s;
    __syncthreads();
    for (int off = 512; off; off >>= 1) {
        if (tid < off) sh[tid] += sh[tid + off];
        __syncthreads();
    }
    if (tid == 0) out[0] = sh[0] * (1.0f / (float)NROWS);
}

// ---------------------------------------------------------------- launch
extern "C" void kernel_launch(void* const* d_in, const int* in_sizes, int n_in,
                              void* d_out, int out_size) {
    const float* z1 = (const float*)d_in[0];
    const float* z2 = (const float*)d_in[1];
    float* out = (float*)d_out;

    static int smem_set = 0;
    if (!smem_set) {
        cudaFuncSetAttribute(k_gemm_tc, cudaFuncAttributeMaxDynamicSharedMemorySize,
                             3 * TILE_BYTES + RED_BYTES + 1024);
        smem_set = 1;
    }

    k_normalize<<<NROWS, 256>>>(z1, z2);
    k_gemm_tc<<<NCTA, 256, 3 * TILE_BYTES + RED_BYTES + 1024>>>();
    k_pair<<<NROWS / 8, 256>>>();
    k_reduce<<<1, 1024>>>(out);
}

// round 8
// speedup vs baseline: 11.5226x; 1.0789x over previous
#include <cuda_runtime.h>
#include <cuda_bf16.h>
#include <cstdint>
#include <math.h>

// NT-Xent loss, N=4096, D=256.
// loss = mean_i( log(sum_{j!=i} e^{2 zn_i.zn_j}) - 2 zn_i.zn_{i^4096} )
// R7: R6 symmetric HMMA GEMM, plus:
//   - pair-dot captured inside the GEMM epilogue (tiles tj == ti+32) -> k_pair deleted
//   - warp-per-row normalize, bf16-only output
//   - fused finish kernel (log + pair + deterministic mean)

#define NROWS 8192
#define NHALF 4096
#define DDIM  256
#define BM 128
#define NTILE 64
#define NCTA 148
#define TILE_BYTES (BM * DDIM * 2)        // 65536
#define RED_BYTES ((4 + 2) * BM * 4)

__device__ __align__(16) __nv_bfloat16 g_zb[NROWS * DDIM];
__device__ float g_rowsum[NROWS];
__device__ float g_pair[NROWS];

// ---------------------------------------------------------------- helpers
__device__ __forceinline__ uint32_t smem_u32(const void* p) {
    uint32_t a;
    asm("{ .reg .u64 t; cvta.to.shared.u64 t, %1; cvt.u32.u64 %0, t; }" : "=r"(a) : "l"(p));
    return a;
}
__device__ __forceinline__ void ldsm_x4(uint32_t addr, uint32_t* r) {
    asm volatile("ldmatrix.sync.aligned.m8n8.x4.shared.b16 {%0,%1,%2,%3}, [%4];"
        : "=r"(r[0]), "=r"(r[1]), "=r"(r[2]), "=r"(r[3]) : "r"(addr));
}
__device__ __forceinline__ void mma16816(float* c, const uint32_t* a, const uint32_t* b) {
    asm volatile("mma.sync.aligned.m16n8k16.row.col.f32.bf16.bf16.f32 "
        "{%0,%1,%2,%3}, {%4,%5,%6,%7}, {%8,%9}, {%0,%1,%2,%3};"
        : "+f"(c[0]), "+f"(c[1]), "+f"(c[2]), "+f"(c[3])
        : "r"(a[0]), "r"(a[1]), "r"(a[2]), "r"(a[3]), "r"(b[0]), "r"(b[1]));
}
__device__ __forceinline__ void cp_async16(uint32_t dst, const void* src) {
    asm volatile("cp.async.cg.shared.global [%0], [%1], 16;" :: "r"(dst), "l"(src));
}
#define CP_COMMIT() asm volatile("cp.async.commit_group;" ::: "memory")
#define CP_WAIT0()  asm volatile("cp.async.wait_group 0;" ::: "memory")

__device__ __forceinline__ uint32_t tile_addr(uint32_t base, int row, int chunk) {
    return base + (uint32_t)row * 512u + (uint32_t)((chunk ^ (row & 7)) << 4);
}
__device__ __forceinline__ int rowof(int p) {
    return (p & 1) ? (NTILE - 1 - (p >> 1)) : (p >> 1);
}
__device__ __forceinline__ void tile_load(uint32_t ubase, int row0, int tid) {
    #pragma unroll
    for (int it = 0; it < 16; it++) {
        int idx = tid + it * 256;
        int r = idx >> 5, c = idx & 31;
        cp_async16(tile_addr(ubase, r, c), g_zb + (size_t)(row0 + r) * DDIM + c * 8);
    }
}

// ---------------------------------------------------------------- normalize (warp/row)
__global__ __launch_bounds__(256) void k_normalize(const float* __restrict__ z1,
                                                   const float* __restrict__ z2) {
    const int row = (blockIdx.x * 256 + threadIdx.x) >> 5;
    const int lane = threadIdx.x & 31;
    const float* src = (row < NHALF) ? (z1 + (size_t)row * DDIM)
                                     : (z2 + (size_t)(row - NHALF) * DDIM);
    float4 v0 = ((const float4*)src)[lane];
    float4 v1 = ((const float4*)src)[lane + 32];
    float ss = v0.x * v0.x + v0.y * v0.y + v0.z * v0.z + v0.w * v0.w
             + v1.x * v1.x + v1.y * v1.y + v1.z * v1.z + v1.w * v1.w;
    #pragma unroll
    for (int o = 16; o; o >>= 1) ss += __shfl_xor_sync(0xFFFFFFFFu, ss, o);
    const float rn = 1.0f / fmaxf(sqrtf(ss), 1e-8f);

    __nv_bfloat16* dst = g_zb + (size_t)row * DDIM;
    __nv_bfloat162 b0 = {__float2bfloat16(v0.x * rn), __float2bfloat16(v0.y * rn)};
    __nv_bfloat162 b1 = {__float2bfloat16(v0.z * rn), __float2bfloat16(v0.w * rn)};
    __nv_bfloat162 b2 = {__float2bfloat16(v1.x * rn), __float2bfloat16(v1.y * rn)};
    __nv_bfloat162 b3 = {__float2bfloat16(v1.z * rn), __float2bfloat16(v1.w * rn)};
    ((__nv_bfloat162*)dst)[lane * 2]            = b0;
    ((__nv_bfloat162*)dst)[lane * 2 + 1]        = b1;
    ((__nv_bfloat162*)dst)[(lane + 32) * 2]     = b2;
    ((__nv_bfloat162*)dst)[(lane + 32) * 2 + 1] = b3;
    if (lane == 0) g_rowsum[row] = 0.0f;
}

// --------------------------------------------- symmetric HMMA GEMM + exp + sums + pair
__global__ __launch_bounds__(256, 1) void k_gemm_tc() {
    extern __shared__ __align__(16) char dyn[];
    const int tid = threadIdx.x;
    const int wid = tid >> 5;
    const int lane = tid & 31;
    const int wm = wid & 1;
    const int wn = wid >> 1;
    const int cta = blockIdx.x;

    uint32_t d32 = smem_u32(dyn);
    char* base = dyn + ((1024u - (d32 & 1023u)) & 1023u);
    const uint32_t uA  = smem_u32(base);
    const uint32_t uB0 = uA + TILE_BYTES;
    const uint32_t uB1 = uA + 2 * TILE_BYTES;
    float* red_row = (float*)(base + 3 * TILE_BYTES);
    float* red_col = red_row + 4 * BM;

    const int count = 14 + (cta < 8 ? 1 : 0);
    int rem = cta * 14 + (cta < 8 ? cta : 8);
    int p = 0;
    for (;;) {
        int L = NTILE - rowof(p);
        if (rem < L) break;
        rem -= L;
        p++;
    }
    int off = rem;

    int ti = rowof(p);
    tile_load(uA, ti * BM, tid);
    tile_load(uB0, (ti + off) * BM, tid);
    CP_COMMIT();
    int cur_ti = ti;

    for (int k = 0; k < count; k++) {
        ti = rowof(p);
        const int tj = ti + off;
        if (ti != cur_ti) {
            tile_load(uA, ti * BM, tid);
            CP_COMMIT();
            cur_ti = ti;
        }
        CP_WAIT0();
        __syncthreads();

        if (k + 1 < count) {
            int p2 = p, o2 = off + 1;
            if (o2 >= NTILE - rowof(p2)) { o2 = 0; p2++; }
            tile_load((k & 1) ? uB0 : uB1, (rowof(p2) + o2) * BM, tid);
            CP_COMMIT();
        }

        const uint32_t uBc = (k & 1) ? uB1 : uB0;
        const int i0 = ti * BM, j0 = tj * BM;
        const bool diag = (ti == tj);
        const bool pairt = (tj == ti + NHALF / BM);

        float acc[4][4][4];
        #pragma unroll
        for (int mf = 0; mf < 4; mf++)
            #pragma unroll
            for (int nf = 0; nf < 4; nf++)
                #pragma unroll
                for (int c = 0; c < 4; c++) acc[mf][nf][c] = 0.0f;

        #pragma unroll 4
        for (int ks = 0; ks < 16; ks++) {
            const int cch = ks * 2 + (lane >> 4);
            uint32_t af[4][4], bf[4][2];
            #pragma unroll
            for (int mf = 0; mf < 4; mf++) {
                int r = wm * 64 + mf * 16 + (lane & 15);
                ldsm_x4(tile_addr(uA, r, cch), af[mf]);
            }
            #pragma unroll
            for (int ng = 0; ng < 2; ng++) {
                int rn = wn * 32 + ng * 16 + (lane & 15);
                uint32_t q[4];
                ldsm_x4(tile_addr(uBc, rn, cch), q);
                bf[ng * 2 + 0][0] = q[0]; bf[ng * 2 + 0][1] = q[2];
                bf[ng * 2 + 1][0] = q[1]; bf[ng * 2 + 1][1] = q[3];
            }
            #pragma unroll
            for (int mf = 0; mf < 4; mf++)
                #pragma unroll
                for (int nf = 0; nf < 4; nf++)
                    mma16816(acc[mf][nf], af[mf], bf[nf]);
        }

        // ---- epilogue: pair capture, exp, diagonal mask, row+col sums ----
        const int rloc = wm * 64 + (lane >> 2);
        const int cloc = wn * 32 + (lane & 3) * 2;
        float cs[8];
        #pragma unroll
        for (int x = 0; x < 8; x++) cs[x] = 0.0f;

        #pragma unroll
        for (int mf = 0; mf < 4; mf++) {
            const int rlo = i0 + rloc + mf * 16;
            const int rhi = rlo + 8;
            float slo = 0.0f, shi = 0.0f;
            #pragma unroll
            for (int nf = 0; nf < 4; nf++) {
                const int col = j0 + cloc + nf * 8;
                if (pairt) {   // sim[i, i^4096] lives on this tile's local diagonal
                    if ((rlo ^ NHALF) == col) {
                        float v = 2.0f * acc[mf][nf][0];
                        g_pair[rlo] = v; g_pair[col] = v;
                    }
                    if ((rlo ^ NHALF) == col + 1) {
                        float v = 2.0f * acc[mf][nf][1];
                        g_pair[rlo] = v; g_pair[col + 1] = v;
                    }
                    if ((rhi ^ NHALF) == col) {
                        float v = 2.0f * acc[mf][nf][2];
                        g_pair[rhi] = v; g_pair[col] = v;
                    }
                    if ((rhi ^ NHALF) == col + 1) {
                        float v = 2.0f * acc[mf][nf][3];
                        g_pair[rhi] = v; g_pair[col + 1] = v;
                    }
                }
                float e0 = __expf(2.0f * acc[mf][nf][0]);
                float e1 = __expf(2.0f * acc[mf][nf][1]);
                float e2 = __expf(2.0f * acc[mf][nf][2]);
                float e3 = __expf(2.0f * acc[mf][nf][3]);
                e0 = (rlo == col)     ? 0.0f : e0;
                e1 = (rlo == col + 1) ? 0.0f : e1;
                e2 = (rhi == col)     ? 0.0f : e2;
                e3 = (rhi == col + 1) ? 0.0f : e3;
                slo += e0 + e1;
                shi += e2 + e3;
                cs[nf * 2]     += e0 + e2;
                cs[nf * 2 + 1] += e1 + e3;
            }
            slo += __shfl_xor_sync(0xFFFFFFFFu, slo, 1);
            slo += __shfl_xor_sync(0xFFFFFFFFu, slo, 2);
            shi += __shfl_xor_sync(0xFFFFFFFFu, shi, 1);
            shi += __shfl_xor_sync(0xFFFFFFFFu, shi, 2);
            if ((lane & 3) == 0) {
                const int lrow = wm * 64 + mf * 16 + (lane >> 2);
                red_row[wn * BM + lrow] = slo;
                red_row[wn * BM + lrow + 8] = shi;
            }
        }
        if (!diag) {
            #pragma unroll
            for (int x = 0; x < 8; x++) {
                cs[x] += __shfl_xor_sync(0xFFFFFFFFu, cs[x], 4);
                cs[x] += __shfl_xor_sync(0xFFFFFFFFu, cs[x], 8);
                cs[x] += __shfl_xor_sync(0xFFFFFFFFu, cs[x], 16);
            }
            if (lane < 4) {
                #pragma unroll
                for (int nf = 0; nf < 4; nf++) {
                    const int c = wn * 32 + nf * 8 + lane * 2;
                    red_col[wm * BM + c]     = cs[nf * 2];
                    red_col[wm * BM + c + 1] = cs[nf * 2 + 1];
                }
            }
        }
        __syncthreads();
        if (tid < BM) {
            float s = red_row[tid] + red_row[BM + tid]
                    + red_row[2 * BM + tid] + red_row[3 * BM + tid];
            atomicAdd(&g_rowsum[i0 + tid], s);
        } else if (!diag) {
            const int c = tid - BM;
            atomicAdd(&g_rowsum[j0 + c], red_col[c] + red_col[BM + c]);
        }

        off++;
        if (off >= NTILE - ti) { off = 0; p++; }
    }
}

// ------------------------------------ finish: log + pair + deterministic mean
__global__ __launch_bounds__(1024) void k_finish(float* __restrict__ out) {
    __shared__ float sh[1024];
    const int tid = threadIdx.x;
    float s = 0.0f;
    #pragma unroll
    for (int u = 0; u < NROWS / 1024; u++) {
        const int r = tid + u * 1024;
        s += logf(g_rowsum[r]) - g_pair[r];
    }
    sh[tid] = s;
    __syncthreads();
    for (int off = 512; off; off >>= 1) {
        if (tid < off) sh[tid] += sh[tid + off];
        __syncthreads();
    }
    if (tid == 0) out[0] = sh[0] * (1.0f / (float)NROWS);
}

// ---------------------------------------------------------------- launch
extern "C" void kernel_launch(void* const* d_in, const int* in_sizes, int n_in,
                              void* d_out, int out_size) {
    const float* z1 = (const float*)d_in[0];
    const float* z2 = (const float*)d_in[1];
    float* out = (float*)d_out;

    static int smem_set = 0;
    if (!smem_set) {
        cudaFuncSetAttribute(k_gemm_tc, cudaFuncAttributeMaxDynamicSharedMemorySize,
                             3 * TILE_BYTES + RED_BYTES + 1024);
        smem_set = 1;
    }

    k_normalize<<<NROWS / 8, 256>>>(z1, z2);
    k_gemm_tc<<<NCTA, 256, 3 * TILE_BYTES + RED_BYTES + 1024>>>();
    k_finish<<<1, 1024>>>(out);
}